// round 2
// baseline (speedup 1.0000x reference)
#include <cuda_runtime.h>
#include <math.h>

// Problem constants
#define C_    192      // channels
#define NTOK  196      // tokens per stream
#define B_    256      // batch
#define L2N   392      // 2N
#define PHI_STRIDE (L2N * C_)   // 75264 floats per batch

// ---------------- scratch (device globals; no allocation) ----------------
__device__ float g_phi[(size_t)B_ * L2N * C_];   // [B][392][192]  (~77 MB)
__device__ float g_WfT1[C_ * C_];                // folded conv1 weight, transposed [i][o]
__device__ float g_WfT2[C_ * C_];
__device__ float g_bf1[C_];
__device__ float g_bf2[C_];
__device__ float g_u3[C_];
__device__ float g_u4s[L2N];
__device__ float g_c0_s;
__device__ float g_W[(size_t)B_ * L2N];          // W[b, l]

// ---------------- packed fp32x2 FMA (FFMA2) ----------------
__device__ __forceinline__ void fma2(float2 &d, const float2 &a, const float2 &b) {
    unsigned long long &dr = reinterpret_cast<unsigned long long &>(d);
    const unsigned long long &ar = reinterpret_cast<const unsigned long long &>(const_cast<float2&>(a));
    const unsigned long long &br = reinterpret_cast<const unsigned long long &>(const_cast<float2&>(b));
    asm("fma.rn.f32x2 %0, %1, %2, %0;" : "+l"(dr) : "l"(ar), "l"(br));
}

// ---------------- tiny precompute kernels ----------------
// Fold BN into conv: WfT[i*C+o] = w[o*C+i] * g[o]/sqrt(v[o]+eps);
// bf[o] = (b[o]-m[o])*inv + be[o]
__global__ void fold_kernel(const float* __restrict__ w, const float* __restrict__ b,
                            const float* __restrict__ g, const float* __restrict__ be,
                            const float* __restrict__ m, const float* __restrict__ v,
                            float* __restrict__ WfT, float* __restrict__ bf)
{
    int tid = blockIdx.x * blockDim.x + threadIdx.x;
    if (tid < C_ * C_) {
        int o = tid / C_, i = tid % C_;
        float inv = g[o] / sqrtf(v[o] + 1e-5f);
        WfT[i * C_ + o] = w[o * C_ + i] * inv;
    }
    if (tid < C_) {
        int o = tid;
        float inv = g[o] / sqrtf(v[o] + 1e-5f);
        bf[o] = (b[o] - m[o]) * inv + be[o];
    }
}

// u3[i] = sum_o w5[o] * w3[o*C+i]
__global__ void u3_kernel(const float* __restrict__ w5, const float* __restrict__ w3)
{
    int i = threadIdx.x;   // 192 threads
    float acc = 0.f;
    for (int o = 0; o < C_; ++o) acc += w5[o] * w3[o * C_ + i];
    g_u3[i] = acc;
}

// u4s[m] = sum_o w5[192+o] * (w4[o*784+m] + w4[o*784+m+392])
__global__ void u4s_kernel(const float* __restrict__ w5, const float* __restrict__ w4)
{
    int mI = threadIdx.x;  // 392 threads
    float acc = 0.f;
    for (int o = 0; o < 784; ++o) {
        float ws = w5[C_ + o];
        acc += ws * (w4[o * 784 + mI] + w4[o * 784 + mI + L2N]);
    }
    g_u4s[mI] = acc;
}

// c0 = dot(w5[0:192], b3) + dot(w5[192:976], b4) + b5
__global__ void c0_kernel(const float* __restrict__ w5, const float* __restrict__ b3,
                          const float* __restrict__ b4, const float* __restrict__ b5)
{
    __shared__ float red[1024];
    int t = threadIdx.x;
    float p = 0.f;
    if (t < C_) p = w5[t] * b3[t];
    else if (t < C_ + 784) p = w5[t] * b4[t - C_];
    red[t] = p;
    __syncthreads();
    for (int s = 512; s > 0; s >>= 1) {
        if (t < s) red[t] += red[t + s];
        __syncthreads();
    }
    if (t == 0) g_c0_s = red[0] + b5[0];
}

// ---------------- phi GEMM: relu(bn(conv1d)) for both streams ----------------
// phi[b, moff+n, o] = relu( sum_i X[b,n,i]*WfT[i,o] + bf[o] )
// Tile: BM=128 rows (b,n flattened), BN=64 output channels, BK=16.
// 128 threads, 8x8 microtile per thread, FFMA2 on (row-pair, col) with B duplicated.
__global__ void __launch_bounds__(128) gemm_phi(const float* __restrict__ x,
                                                const float* __restrict__ y)
{
    const int stream = blockIdx.z;
    const float* __restrict__ A    = stream ? y : x;
    const float* __restrict__ Bw   = stream ? g_WfT2 : g_WfT1;
    const float* __restrict__ bias = stream ? g_bf2 : g_bf1;
    const int moff = stream ? NTOK : 0;

    __shared__ float  As[16][128];      // [k][m]
    __shared__ float2 Bsd[16][64];      // [k][n], value duplicated {b,b}

    const int tid = threadIdx.x;
    const int tm = tid >> 3;            // 0..15  (8-row group)
    const int tn = tid & 7;             // 0..7   (8-col group)
    const int row0 = blockIdx.x * 128;
    const int n0   = blockIdx.y * 64;

    // global load mapping
    const float4* Ag = reinterpret_cast<const float4*>(A + (size_t)(row0 + tid) * C_);
    const int f1  = tid + 128;
    const int kb0 = tid >> 4, nb0 = (tid & 15) << 2;   // k 0..7
    const int kb1 = f1  >> 4, nb1 = (f1  & 15) << 2;   // k 8..15

    float2 acc[4][8];
    #pragma unroll
    for (int i = 0; i < 4; ++i)
        #pragma unroll
        for (int j = 0; j < 8; ++j) acc[i][j] = make_float2(0.f, 0.f);

    // prefetch tile 0
    float4 pa0 = Ag[0], pa1 = Ag[1], pa2 = Ag[2], pa3 = Ag[3];
    float4 pb0 = *reinterpret_cast<const float4*>(Bw + kb0 * C_ + n0 + nb0);
    float4 pb1 = *reinterpret_cast<const float4*>(Bw + kb1 * C_ + n0 + nb1);

    #pragma unroll 1
    for (int kt = 0; kt < 12; ++kt) {
        // stage smem
        As[ 0][tid] = pa0.x; As[ 1][tid] = pa0.y; As[ 2][tid] = pa0.z; As[ 3][tid] = pa0.w;
        As[ 4][tid] = pa1.x; As[ 5][tid] = pa1.y; As[ 6][tid] = pa1.z; As[ 7][tid] = pa1.w;
        As[ 8][tid] = pa2.x; As[ 9][tid] = pa2.y; As[10][tid] = pa2.z; As[11][tid] = pa2.w;
        As[12][tid] = pa3.x; As[13][tid] = pa3.y; As[14][tid] = pa3.z; As[15][tid] = pa3.w;
        Bsd[kb0][nb0 + 0] = make_float2(pb0.x, pb0.x);
        Bsd[kb0][nb0 + 1] = make_float2(pb0.y, pb0.y);
        Bsd[kb0][nb0 + 2] = make_float2(pb0.z, pb0.z);
        Bsd[kb0][nb0 + 3] = make_float2(pb0.w, pb0.w);
        Bsd[kb1][nb1 + 0] = make_float2(pb1.x, pb1.x);
        Bsd[kb1][nb1 + 1] = make_float2(pb1.y, pb1.y);
        Bsd[kb1][nb1 + 2] = make_float2(pb1.z, pb1.z);
        Bsd[kb1][nb1 + 3] = make_float2(pb1.w, pb1.w);
        __syncthreads();

        if (kt < 11) {
            const int q = (kt + 1) * 4;
            pa0 = Ag[q + 0]; pa1 = Ag[q + 1]; pa2 = Ag[q + 2]; pa3 = Ag[q + 3];
            const int k0 = (kt + 1) * 16;
            pb0 = *reinterpret_cast<const float4*>(Bw + (k0 + kb0) * C_ + n0 + nb0);
            pb1 = *reinterpret_cast<const float4*>(Bw + (k0 + kb1) * C_ + n0 + nb1);
        }

        #pragma unroll
        for (int k = 0; k < 16; ++k) {
            float4 a0 = *reinterpret_cast<const float4*>(&As[k][tm * 8]);
            float4 a1 = *reinterpret_cast<const float4*>(&As[k][tm * 8 + 4]);
            float2 ap[4];
            ap[0] = make_float2(a0.x, a0.y);
            ap[1] = make_float2(a0.z, a0.w);
            ap[2] = make_float2(a1.x, a1.y);
            ap[3] = make_float2(a1.z, a1.w);
            float2 bd[8];
            *reinterpret_cast<float4*>(&bd[0]) = *reinterpret_cast<const float4*>(&Bsd[k][tn * 8 + 0]);
            *reinterpret_cast<float4*>(&bd[2]) = *reinterpret_cast<const float4*>(&Bsd[k][tn * 8 + 2]);
            *reinterpret_cast<float4*>(&bd[4]) = *reinterpret_cast<const float4*>(&Bsd[k][tn * 8 + 4]);
            *reinterpret_cast<float4*>(&bd[6]) = *reinterpret_cast<const float4*>(&Bsd[k][tn * 8 + 6]);
            #pragma unroll
            for (int j = 0; j < 8; ++j)
                #pragma unroll
                for (int i = 0; i < 4; ++i)
                    fma2(acc[i][j], ap[i], bd[j]);   // {row2i, row2i+1} x col j
        }
        __syncthreads();
    }

    // epilogue: bias + relu, scatter to phi[b][moff+n][c]
    float bv[8];
    #pragma unroll
    for (int j = 0; j < 8; ++j) bv[j] = bias[n0 + tn * 8 + j];

    #pragma unroll
    for (int i = 0; i < 4; ++i) {
        #pragma unroll
        for (int h = 0; h < 2; ++h) {
            int row = row0 + tm * 8 + 2 * i + h;
            int bI  = row / NTOK;
            int n   = row - bI * NTOK;
            float* dst = g_phi + ((size_t)bI * L2N + moff + n) * C_ + n0 + tn * 8;
            float vv[8];
            #pragma unroll
            for (int j = 0; j < 8; ++j) {
                float val = (h ? acc[i][j].y : acc[i][j].x) + bv[j];
                vv[j] = fmaxf(val, 0.f);
            }
            *reinterpret_cast<float4*>(dst)     = make_float4(vv[0], vv[1], vv[2], vv[3]);
            *reinterpret_cast<float4*>(dst + 4) = make_float4(vv[4], vv[5], vv[6], vv[7]);
        }
    }
}

// ---------------- fused s + W kernel: one block per batch ----------------
// s[c]   = sum_m u4s[m] * phi[b,m,c]
// W[b,l] = c0 + sum_c (u3[c] + s[c]) * phi[b,l,c]
__global__ void __launch_bounds__(384) sw_kernel()
{
    const int b = blockIdx.x;
    __shared__ float u4s_s[L2N];
    __shared__ float part[384];
    __shared__ float coef[C_];

    const int tid = threadIdx.x;
    for (int i = tid; i < L2N; i += 384) u4s_s[i] = g_u4s[i];
    __syncthreads();

    const float* __restrict__ pb = g_phi + (size_t)b * PHI_STRIDE;

    {   // pass 1: column sums (s)
        const int c = tid % C_;
        const int h = tid / C_;      // 0 or 1, splits m range
        const int m0 = h * NTOK;
        float acc = 0.f;
        #pragma unroll 4
        for (int m = 0; m < NTOK; ++m)
            acc += u4s_s[m0 + m] * pb[(size_t)(m0 + m) * C_ + c];
        part[tid] = acc;
    }
    __syncthreads();
    if (tid < C_) coef[tid] = g_u3[tid] + part[tid] + part[tid + C_];
    __syncthreads();

    // pass 2: per-l dot products (W), one warp per l
    const int warp = tid >> 5, lane = tid & 31;   // 12 warps
    const float cc0 = g_c0_s;
    for (int l = warp; l < L2N; l += 12) {
        const float* row = pb + (size_t)l * C_;
        float p = 0.f;
        #pragma unroll
        for (int j = 0; j < 6; ++j) {
            int c = lane + 32 * j;
            p += coef[c] * row[c];
        }
        #pragma unroll
        for (int off = 16; off > 0; off >>= 1)
            p += __shfl_xor_sync(0xffffffffu, p, off);
        if (lane == 0) g_W[(size_t)b * L2N + l] = p + cc0;
    }
}

// ---------------- output: out[b,c,n] = x[b,n,c]*W[b,n] + y[b,n,c]*W[b,n+196] ----------------
__global__ void out_kernel(const float* __restrict__ x, const float* __restrict__ y,
                           float* __restrict__ out)
{
    const int b  = blockIdx.z;
    const int c0 = blockIdx.y * 32;
    const int n0 = blockIdx.x * 32;
    __shared__ float xs[32][33], ys[32][33];
    const int tx = threadIdx.x, ty = threadIdx.y;

    int n = n0 + ty;
    if (n < NTOK) {
        size_t src = ((size_t)b * NTOK + n) * C_ + c0 + tx;   // coalesced in c
        xs[ty][tx] = x[src];
        ys[ty][tx] = y[src];
    }
    __syncthreads();

    int nn = n0 + tx;
    if (nn < NTOK) {
        float wl = g_W[(size_t)b * L2N + nn];
        float wr = g_W[(size_t)b * L2N + NTOK + nn];
        out[((size_t)b * C_ + c0 + ty) * NTOK + nn] = xs[tx][ty] * wl + ys[tx][ty] * wr;
    }
}

// ---------------- launch ----------------
extern "C" void kernel_launch(void* const* d_in, const int* in_sizes, int n_in,
                              void* d_out, int out_size)
{
    const float* x   = (const float*)d_in[0];
    const float* y   = (const float*)d_in[1];
    const float* w1  = (const float*)d_in[2];
    const float* b1  = (const float*)d_in[3];
    const float* g1  = (const float*)d_in[4];
    const float* be1 = (const float*)d_in[5];
    const float* m1  = (const float*)d_in[6];
    const float* v1  = (const float*)d_in[7];
    const float* w2  = (const float*)d_in[8];
    const float* b2  = (const float*)d_in[9];
    const float* g2  = (const float*)d_in[10];
    const float* be2 = (const float*)d_in[11];
    const float* m2  = (const float*)d_in[12];
    const float* v2  = (const float*)d_in[13];
    const float* w3  = (const float*)d_in[14];
    const float* b3  = (const float*)d_in[15];
    const float* w4  = (const float*)d_in[16];
    const float* b4  = (const float*)d_in[17];
    const float* w5  = (const float*)d_in[18];
    const float* b5  = (const float*)d_in[19];
    float* out = (float*)d_out;

    float *WfT1, *WfT2, *bf1, *bf2;
    cudaGetSymbolAddress((void**)&WfT1, g_WfT1);
    cudaGetSymbolAddress((void**)&WfT2, g_WfT2);
    cudaGetSymbolAddress((void**)&bf1,  g_bf1);
    cudaGetSymbolAddress((void**)&bf2,  g_bf2);

    fold_kernel<<<(C_ * C_ + 255) / 256, 256>>>(w1, b1, g1, be1, m1, v1, WfT1, bf1);
    fold_kernel<<<(C_ * C_ + 255) / 256, 256>>>(w2, b2, g2, be2, m2, v2, WfT2, bf2);
    u3_kernel<<<1, C_>>>(w5, w3);
    u4s_kernel<<<1, L2N>>>(w5, w4);
    c0_kernel<<<1, 1024>>>(w5, b3, b4, b5);

    gemm_phi<<<dim3(392, 3, 2), 128>>>(x, y);
    sw_kernel<<<B_, 384>>>();
    out_kernel<<<dim3(7, 6, B_), dim3(32, 32)>>>(x, y, out);
}

// round 4
// speedup vs baseline: 2.0553x; 2.0553x over previous
#include <cuda_runtime.h>
#include <math.h>

// Problem constants
#define C_    192      // channels
#define NTOK  196      // tokens per stream
#define B_    256      // batch
#define L2N   392      // 2N
#define PHI_STRIDE (L2N * C_)   // 75264 floats per batch

// ---------------- scratch (device globals; no allocation) ----------------
__device__ float g_phi[(size_t)B_ * L2N * C_];   // [B][392][192]  (~77 MB)
__device__ float g_WfT1[C_ * C_];                // folded conv1 weight, transposed [i][o]
__device__ float g_WfT2[C_ * C_];
__device__ float g_bf1[C_];
__device__ float g_bf2[C_];
__device__ float g_u3[C_];
__device__ float g_u4s[L2N];
__device__ float g_u4s_part[56][L2N];
__device__ float g_c0_s;
__device__ float g_W[(size_t)B_ * L2N];          // W[b, l]

// ---------------- packed fp32x2 helpers ----------------
__device__ __forceinline__ void fma2(float2 &d, const float2 &a, const float2 &b) {
    unsigned long long &dr = reinterpret_cast<unsigned long long &>(d);
    const unsigned long long &ar = reinterpret_cast<const unsigned long long &>(const_cast<float2&>(a));
    const unsigned long long &br = reinterpret_cast<const unsigned long long &>(const_cast<float2&>(b));
    asm("fma.rn.f32x2 %0, %1, %2, %0;" : "+l"(dr) : "l"(ar), "l"(br));
}
__device__ __forceinline__ float2 dup2(float v) {
    unsigned long long r;
    asm("mov.b64 %0, {%1, %1};" : "=l"(r) : "f"(v));
    return reinterpret_cast<float2&>(r);
}

// ---------------- tiny precompute kernels ----------------
__global__ void fold_kernel(const float* __restrict__ w, const float* __restrict__ b,
                            const float* __restrict__ g, const float* __restrict__ be,
                            const float* __restrict__ m, const float* __restrict__ v,
                            float* __restrict__ WfT, float* __restrict__ bf)
{
    int tid = blockIdx.x * blockDim.x + threadIdx.x;
    if (tid < C_ * C_) {
        int o = tid / C_, i = tid % C_;
        float inv = g[o] / sqrtf(v[o] + 1e-5f);
        WfT[i * C_ + o] = w[o * C_ + i] * inv;
    }
    if (tid < C_) {
        int o = tid;
        float inv = g[o] / sqrtf(v[o] + 1e-5f);
        bf[o] = (b[o] - m[o]) * inv + be[o];
    }
}

// u3[i] = sum_o w5[o] * w3[o*C+i]  (576 threads: 3-way split over o)
__global__ void u3_kernel(const float* __restrict__ w5, const float* __restrict__ w3)
{
    __shared__ float part[576];
    int tid = threadIdx.x;
    int i = tid % C_;
    int h = tid / C_;          // 0..2
    float acc = 0.f;
    for (int o = h * 64; o < h * 64 + 64; ++o)
        acc += w5[o] * w3[o * C_ + i];
    part[tid] = acc;
    __syncthreads();
    if (tid < C_) g_u3[tid] = part[tid] + part[tid + C_] + part[tid + 2 * C_];
}

// u4s[m] = sum_o w5[192+o] * (w4[o*784+m] + w4[o*784+m+392]) — split-o, 56 blocks
__global__ void u4s_part_kernel(const float* __restrict__ w5, const float* __restrict__ w4)
{
    const int j = blockIdx.x;       // 0..55, owns o in [j*14, j*14+14)
    const int m = threadIdx.x;      // 0..391
    float acc = 0.f;
    #pragma unroll
    for (int oo = 0; oo < 14; ++oo) {
        int o = j * 14 + oo;
        float ws = w5[C_ + o];
        acc += ws * (w4[o * 784 + m] + w4[o * 784 + m + L2N]);
    }
    g_u4s_part[j][m] = acc;
}
__global__ void u4s_reduce_kernel()
{
    const int m = threadIdx.x;
    float acc = 0.f;
    #pragma unroll
    for (int j = 0; j < 56; ++j) acc += g_u4s_part[j][m];
    g_u4s[m] = acc;
}

// c0 = dot(w5[0:192], b3) + dot(w5[192:976], b4) + b5
__global__ void c0_kernel(const float* __restrict__ w5, const float* __restrict__ b3,
                          const float* __restrict__ b4, const float* __restrict__ b5)
{
    __shared__ float red[1024];
    int t = threadIdx.x;
    float p = 0.f;
    if (t < C_) p = w5[t] * b3[t];
    else if (t < C_ + 784) p = w5[t] * b4[t - C_];
    red[t] = p;
    __syncthreads();
    for (int s = 512; s > 0; s >>= 1) {
        if (t < s) red[t] += red[t + s];
        __syncthreads();
    }
    if (t == 0) g_c0_s = red[0] + b5[0];
}

// ---------------- phi GEMM: relu(bn(conv1d)) for both streams ----------------
// Block tile: 128 rows x 192 cols (full N), BK=16, 192 threads.
// Microtile: 8 rows x 16 cols per thread. FFMA2 pairs adjacent COLUMNS:
//   acc{c,c+1} += dup{a,a} * {b_c, b_c+1}
// B stored as plain floats in interleaved float4 layout Bs4[k][q][cn] so that
// per-instruction lane addresses are consecutive float4s (no 4/6-way aliasing).
// A duplicated in-register via mov.b64 (alu pipe, free under FMA issue budget).
__global__ void __launch_bounds__(192, 1) gemm_phi(const float* __restrict__ x,
                                                   const float* __restrict__ y)
{
    const int stream = blockIdx.z;
    const float* __restrict__ A    = stream ? y : x;
    const float* __restrict__ Bw   = stream ? g_WfT2 : g_WfT1;
    const float* __restrict__ bias = stream ? g_bf2 : g_bf1;
    const int moff = stream ? NTOK : 0;

    __shared__ float  As[16][128];        // [k][row]  8 KB
    __shared__ float4 Bs4[16][4][12];     // [k][q][cn] 12 KB; holds B[k][cn*16+4q .. +3]

    const int tid = threadIdx.x;
    const int tn = tid % 12;              // col group: cols tn*16 .. tn*16+15
    const int rm = tid / 12;              // row group: rows rm*8 .. rm*8+7
    const int row0 = blockIdx.x * 128;

    // A loader: threads 0..127, thread t owns global row row0+t, loads 4 float4 per k-tile
    const float4* Ag = reinterpret_cast<const float4*>(A + (size_t)(row0 + tid) * C_);
    // B loader: 4 float4 per thread per k-tile. f = tid + 192*j -> kk = f/48, c4 = f%48
    int bkk[4], bq[4], bcn[4], bc4[4];
    #pragma unroll
    for (int j = 0; j < 4; ++j) {
        int f = tid + 192 * j;
        bkk[j] = f / 48;
        bc4[j] = f % 48;
        bq[j]  = bc4[j] & 3;
        bcn[j] = bc4[j] >> 2;
    }

    float2 acc[8][8];
    #pragma unroll
    for (int i = 0; i < 8; ++i)
        #pragma unroll
        for (int j = 0; j < 8; ++j) acc[i][j] = make_float2(0.f, 0.f);

    // prefetch tile 0
    float4 pa[4], pb[4];
    if (tid < 128) {
        #pragma unroll
        for (int j = 0; j < 4; ++j) pa[j] = Ag[j];
    }
    #pragma unroll
    for (int j = 0; j < 4; ++j)
        pb[j] = *reinterpret_cast<const float4*>(Bw + bkk[j] * C_ + bc4[j] * 4);

    #pragma unroll 1
    for (int kt = 0; kt < 12; ++kt) {
        if (tid < 128) {
            #pragma unroll
            for (int j = 0; j < 4; ++j) {
                As[4 * j + 0][tid] = pa[j].x;
                As[4 * j + 1][tid] = pa[j].y;
                As[4 * j + 2][tid] = pa[j].z;
                As[4 * j + 3][tid] = pa[j].w;
            }
        }
        #pragma unroll
        for (int j = 0; j < 4; ++j)
            Bs4[bkk[j]][bq[j]][bcn[j]] = pb[j];
        __syncthreads();

        if (kt < 11) {
            const int q = (kt + 1) * 4;
            if (tid < 128) {
                #pragma unroll
                for (int j = 0; j < 4; ++j) pa[j] = Ag[q + j];
            }
            const int k0 = (kt + 1) * 16;
            #pragma unroll
            for (int j = 0; j < 4; ++j)
                pb[j] = *reinterpret_cast<const float4*>(Bw + (k0 + bkk[j]) * C_ + bc4[j] * 4);
        }

        #pragma unroll
        for (int k = 0; k < 16; ++k) {
            // A: 8 scalars (2 LDS.128), duplicate in-register
            float4 a0 = *reinterpret_cast<const float4*>(&As[k][rm * 8]);
            float4 a1 = *reinterpret_cast<const float4*>(&As[k][rm * 8 + 4]);
            float2 ad[8];
            ad[0] = dup2(a0.x); ad[1] = dup2(a0.y); ad[2] = dup2(a0.z); ad[3] = dup2(a0.w);
            ad[4] = dup2(a1.x); ad[5] = dup2(a1.y); ad[6] = dup2(a1.z); ad[7] = dup2(a1.w);
            // B: 16 cols = 4 float4, natural col-pairs as float2
            float4 bb[4];
            bb[0] = Bs4[k][0][tn];
            bb[1] = Bs4[k][1][tn];
            bb[2] = Bs4[k][2][tn];
            bb[3] = Bs4[k][3][tn];
            const float2* bp = reinterpret_cast<const float2*>(bb);
            #pragma unroll
            for (int j = 0; j < 8; ++j)
                #pragma unroll
                for (int i = 0; i < 8; ++i)
                    fma2(acc[i][j], ad[i], bp[j]);
        }
        __syncthreads();
    }

    // epilogue: bias + relu, scatter to phi[b][moff+n][tn*16..]
    float4 bias4[4];
    #pragma unroll
    for (int q = 0; q < 4; ++q)
        bias4[q] = *reinterpret_cast<const float4*>(bias + tn * 16 + 4 * q);
    const float* bvf = reinterpret_cast<const float*>(bias4);

    #pragma unroll
    for (int i = 0; i < 8; ++i) {
        int row = row0 + rm * 8 + i;
        int bI  = row / NTOK;
        int n   = row - bI * NTOK;
        float* dst = g_phi + ((size_t)bI * L2N + moff + n) * C_ + tn * 16;
        float vv[16];
        #pragma unroll
        for (int j = 0; j < 8; ++j) {
            vv[2 * j]     = fmaxf(acc[i][j].x + bvf[2 * j],     0.f);
            vv[2 * j + 1] = fmaxf(acc[i][j].y + bvf[2 * j + 1], 0.f);
        }
        #pragma unroll
        for (int q = 0; q < 4; ++q)
            *reinterpret_cast<float4*>(dst + 4 * q) =
                make_float4(vv[4 * q], vv[4 * q + 1], vv[4 * q + 2], vv[4 * q + 3]);
    }
}

// ---------------- fused s + W kernel: one block per batch ----------------
__global__ void __launch_bounds__(384) sw_kernel()
{
    const int b = blockIdx.x;
    __shared__ float u4s_s[L2N];
    __shared__ float part[384];
    __shared__ float coef[C_];

    const int tid = threadIdx.x;
    for (int i = tid; i < L2N; i += 384) u4s_s[i] = g_u4s[i];
    __syncthreads();

    const float* __restrict__ pb = g_phi + (size_t)b * PHI_STRIDE;

    {   // pass 1: column sums (s)
        const int c = tid % C_;
        const int h = tid / C_;
        const int m0 = h * NTOK;
        float acc = 0.f;
        #pragma unroll 4
        for (int m = 0; m < NTOK; ++m)
            acc += u4s_s[m0 + m] * pb[(size_t)(m0 + m) * C_ + c];
        part[tid] = acc;
    }
    __syncthreads();
    if (tid < C_) coef[tid] = g_u3[tid] + part[tid] + part[tid + C_];
    __syncthreads();

    // pass 2: per-l dot products (W), one warp per l
    const int warp = tid >> 5, lane = tid & 31;
    const float cc0 = g_c0_s;
    for (int l = warp; l < L2N; l += 12) {
        const float* row = pb + (size_t)l * C_;
        float p = 0.f;
        #pragma unroll
        for (int j = 0; j < 6; ++j) {
            int c = lane + 32 * j;
            p += coef[c] * row[c];
        }
        #pragma unroll
        for (int off = 16; off > 0; off >>= 1)
            p += __shfl_xor_sync(0xffffffffu, p, off);
        if (lane == 0) g_W[(size_t)b * L2N + l] = p + cc0;
    }
}

// ---------------- output: out[b,c,n] = x[b,n,c]*W[b,n] + y[b,n,c]*W[b,n+196] ----------------
__global__ void out_kernel(const float* __restrict__ x, const float* __restrict__ y,
                           float* __restrict__ out)
{
    const int b  = blockIdx.z;
    const int c0 = blockIdx.y * 32;
    const int n0 = blockIdx.x * 32;
    __shared__ float xs[32][33], ys[32][33];
    const int tx = threadIdx.x, ty = threadIdx.y;

    int n = n0 + ty;
    if (n < NTOK) {
        size_t src = ((size_t)b * NTOK + n) * C_ + c0 + tx;
        xs[ty][tx] = x[src];
        ys[ty][tx] = y[src];
    }
    __syncthreads();

    int nn = n0 + tx;
    if (nn < NTOK) {
        float wl = g_W[(size_t)b * L2N + nn];
        float wr = g_W[(size_t)b * L2N + NTOK + nn];
        out[((size_t)b * C_ + c0 + ty) * NTOK + nn] = xs[tx][ty] * wl + ys[tx][ty] * wr;
    }
}

// ---------------- launch ----------------
extern "C" void kernel_launch(void* const* d_in, const int* in_sizes, int n_in,
                              void* d_out, int out_size)
{
    const float* x   = (const float*)d_in[0];
    const float* y   = (const float*)d_in[1];
    const float* w1  = (const float*)d_in[2];
    const float* b1  = (const float*)d_in[3];
    const float* g1  = (const float*)d_in[4];
    const float* be1 = (const float*)d_in[5];
    const float* m1  = (const float*)d_in[6];
    const float* v1  = (const float*)d_in[7];
    const float* w2  = (const float*)d_in[8];
    const float* b2  = (const float*)d_in[9];
    const float* g2  = (const float*)d_in[10];
    const float* be2 = (const float*)d_in[11];
    const float* m2  = (const float*)d_in[12];
    const float* v2  = (const float*)d_in[13];
    const float* w3  = (const float*)d_in[14];
    const float* b3  = (const float*)d_in[15];
    const float* w4  = (const float*)d_in[16];
    const float* b4  = (const float*)d_in[17];
    const float* w5  = (const float*)d_in[18];
    const float* b5  = (const float*)d_in[19];
    float* out = (float*)d_out;

    float *WfT1, *WfT2, *bf1, *bf2;
    cudaGetSymbolAddress((void**)&WfT1, g_WfT1);
    cudaGetSymbolAddress((void**)&WfT2, g_WfT2);
    cudaGetSymbolAddress((void**)&bf1,  g_bf1);
    cudaGetSymbolAddress((void**)&bf2,  g_bf2);

    fold_kernel<<<(C_ * C_ + 255) / 256, 256>>>(w1, b1, g1, be1, m1, v1, WfT1, bf1);
    fold_kernel<<<(C_ * C_ + 255) / 256, 256>>>(w2, b2, g2, be2, m2, v2, WfT2, bf2);
    u3_kernel<<<1, 576>>>(w5, w3);
    u4s_part_kernel<<<56, L2N>>>(w5, w4);
    u4s_reduce_kernel<<<1, L2N>>>();
    c0_kernel<<<1, 1024>>>(w5, b3, b4, b5);

    gemm_phi<<<dim3(392, 1, 2), 192>>>(x, y);
    sw_kernel<<<B_, 384>>>();
    out_kernel<<<dim3(7, 6, B_), dim3(32, 32)>>>(x, y, out);
}

// round 8
// speedup vs baseline: 2.3414x; 1.1392x over previous
#include <cuda_runtime.h>
#include <math.h>

// Problem constants
#define C_    192      // channels
#define NTOK  196      // tokens per stream
#define B_    256      // batch
#define L2N   392      // 2N
#define PHI_STRIDE (L2N * C_)   // 75264 floats per batch

// ---------------- scratch (device globals; no allocation) ----------------
__device__ float g_phi[(size_t)B_ * L2N * C_];   // [B][392][192]  (~77 MB)
__device__ float g_WfT1[C_ * C_];                // folded conv1 weight, transposed [i][o]
__device__ float g_WfT2[C_ * C_];
__device__ float g_bf1[C_];
__device__ float g_bf2[C_];
__device__ float g_u3[C_];
__device__ float g_u4s[L2N];
__device__ float g_u4s_part[56][L2N];
__device__ float g_c0_s;
__device__ float g_W[(size_t)B_ * L2N];          // W[b, l]

// ---------------- packed fp32x2 helpers ----------------
__device__ __forceinline__ void fma2(float2 &d, const float2 &a, const float2 &b) {
    unsigned long long &dr = reinterpret_cast<unsigned long long &>(d);
    const unsigned long long &ar = reinterpret_cast<const unsigned long long &>(const_cast<float2&>(a));
    const unsigned long long &br = reinterpret_cast<const unsigned long long &>(const_cast<float2&>(b));
    asm("fma.rn.f32x2 %0, %1, %2, %0;" : "+l"(dr) : "l"(ar), "l"(br));
}
__device__ __forceinline__ float2 dup2(float v) {
    unsigned long long r;
    asm("mov.b64 %0, {%1, %1};" : "=l"(r) : "f"(v));
    return reinterpret_cast<float2&>(r);
}

// ---------------- tiny precompute kernels ----------------
__global__ void fold_kernel(const float* __restrict__ w, const float* __restrict__ b,
                            const float* __restrict__ g, const float* __restrict__ be,
                            const float* __restrict__ m, const float* __restrict__ v,
                            float* __restrict__ WfT, float* __restrict__ bf)
{
    int tid = blockIdx.x * blockDim.x + threadIdx.x;
    if (tid < C_ * C_) {
        int o = tid / C_, i = tid % C_;
        float inv = g[o] / sqrtf(v[o] + 1e-5f);
        WfT[i * C_ + o] = w[o * C_ + i] * inv;
    }
    if (tid < C_) {
        int o = tid;
        float inv = g[o] / sqrtf(v[o] + 1e-5f);
        bf[o] = (b[o] - m[o]) * inv + be[o];
    }
}

// u3[i] = sum_o w5[o] * w3[o*C+i]  (576 threads: 3-way split over o)
__global__ void u3_kernel(const float* __restrict__ w5, const float* __restrict__ w3)
{
    __shared__ float part[576];
    int tid = threadIdx.x;
    int i = tid % C_;
    int h = tid / C_;          // 0..2
    float acc = 0.f;
    for (int o = h * 64; o < h * 64 + 64; ++o)
        acc += w5[o] * w3[o * C_ + i];
    part[tid] = acc;
    __syncthreads();
    if (tid < C_) g_u3[tid] = part[tid] + part[tid + C_] + part[tid + 2 * C_];
}

// u4s[m] = sum_o w5[192+o] * (w4[o*784+m] + w4[o*784+m+392]) — split-o, 56 blocks
__global__ void u4s_part_kernel(const float* __restrict__ w5, const float* __restrict__ w4)
{
    const int j = blockIdx.x;       // 0..55, owns o in [j*14, j*14+14)
    const int m = threadIdx.x;      // 0..391
    float acc = 0.f;
    #pragma unroll
    for (int oo = 0; oo < 14; ++oo) {
        int o = j * 14 + oo;
        float ws = w5[C_ + o];
        acc += ws * (w4[o * 784 + m] + w4[o * 784 + m + L2N]);
    }
    g_u4s_part[j][m] = acc;
}
__global__ void u4s_reduce_kernel()
{
    const int m = threadIdx.x;
    float acc = 0.f;
    #pragma unroll
    for (int j = 0; j < 56; ++j) acc += g_u4s_part[j][m];
    g_u4s[m] = acc;
}

// c0 = dot(w5[0:192], b3) + dot(w5[192:976], b4) + b5
__global__ void c0_kernel(const float* __restrict__ w5, const float* __restrict__ b3,
                          const float* __restrict__ b4, const float* __restrict__ b5)
{
    __shared__ float red[1024];
    int t = threadIdx.x;
    float p = 0.f;
    if (t < C_) p = w5[t] * b3[t];
    else if (t < C_ + 784) p = w5[t] * b4[t - C_];
    red[t] = p;
    __syncthreads();
    for (int s = 512; s > 0; s >>= 1) {
        if (t < s) red[t] += red[t + s];
        __syncthreads();
    }
    if (t == 0) g_c0_s = red[0] + b5[0];
}

// ---------------- phi GEMM: relu(bn(conv1d)) for both streams ----------------
// Block tile: 128 rows x 192 cols, BK=16, 256 threads = 8 warps (2 per SMSP,
// balanced FMA-pipe load — the 192-thread version left 2 SMSPs half idle).
// Microtile: 8 rows x 12 cols per thread. FFMA2 pairs adjacent COLUMNS.
// B smem: float4 Bs4[k][q][cn], q=0..2, cn=0..15 -> cols cn*12+4q..+3; a warp's
// 16 'cn' lanes read consecutive float4s (2 wavefronts, broadcast x2).
__global__ void __launch_bounds__(256, 1) gemm_phi(const float* __restrict__ x,
                                                   const float* __restrict__ y)
{
    const int stream = blockIdx.z;
    const float* __restrict__ A    = stream ? y : x;
    const float* __restrict__ Bw   = stream ? g_WfT2 : g_WfT1;
    const float* __restrict__ bias = stream ? g_bf2 : g_bf1;
    const int moff = stream ? NTOK : 0;

    __shared__ float  As[16][128];        // [k][row]   8 KB
    __shared__ float4 Bs4[16][3][16];     // [k][q][cn] 12 KB

    const int tid = threadIdx.x;
    const int tn = tid % 16;              // col group: cols tn*12 .. tn*12+11
    const int rm = tid / 16;              // row group: rows rm*8 .. rm*8+7
    const int row0 = blockIdx.x * 128;

    // A loader: threads 0..127, thread t owns global row row0+t, 4 float4 per k-tile
    const float4* Ag = reinterpret_cast<const float4*>(A + (size_t)(row0 + tid) * C_);
    // B loader: 3 float4 per thread per k-tile. f = tid + 256*j -> kk = f/48, c4 = f%48
    int bkk[3], bq[3], bcn[3], bc4[3];
    #pragma unroll
    for (int j = 0; j < 3; ++j) {
        int f = tid + 256 * j;
        bkk[j] = f / 48;
        bc4[j] = f % 48;
        bq[j]  = bc4[j] % 3;
        bcn[j] = bc4[j] / 3;
    }

    float2 acc[8][6];
    #pragma unroll
    for (int i = 0; i < 8; ++i)
        #pragma unroll
        for (int j = 0; j < 6; ++j) acc[i][j] = make_float2(0.f, 0.f);

    // prefetch tile 0
    float4 pa[4], pb[3];
    if (tid < 128) {
        #pragma unroll
        for (int j = 0; j < 4; ++j) pa[j] = Ag[j];
    }
    #pragma unroll
    for (int j = 0; j < 3; ++j)
        pb[j] = *reinterpret_cast<const float4*>(Bw + bkk[j] * C_ + bc4[j] * 4);

    #pragma unroll 1
    for (int kt = 0; kt < 12; ++kt) {
        if (tid < 128) {
            #pragma unroll
            for (int j = 0; j < 4; ++j) {
                As[4 * j + 0][tid] = pa[j].x;
                As[4 * j + 1][tid] = pa[j].y;
                As[4 * j + 2][tid] = pa[j].z;
                As[4 * j + 3][tid] = pa[j].w;
            }
        }
        #pragma unroll
        for (int j = 0; j < 3; ++j)
            Bs4[bkk[j]][bq[j]][bcn[j]] = pb[j];
        __syncthreads();

        if (kt < 11) {
            const int q = (kt + 1) * 4;
            if (tid < 128) {
                #pragma unroll
                for (int j = 0; j < 4; ++j) pa[j] = Ag[q + j];
            }
            const int k0 = (kt + 1) * 16;
            #pragma unroll
            for (int j = 0; j < 3; ++j)
                pb[j] = *reinterpret_cast<const float4*>(Bw + (k0 + bkk[j]) * C_ + bc4[j] * 4);
        }

        #pragma unroll
        for (int k = 0; k < 16; ++k) {
            // A: 8 scalars (2 LDS.128), duplicate in-register (alu-pipe MOVs)
            float4 a0 = *reinterpret_cast<const float4*>(&As[k][rm * 8]);
            float4 a1 = *reinterpret_cast<const float4*>(&As[k][rm * 8 + 4]);
            float2 ad[8];
            ad[0] = dup2(a0.x); ad[1] = dup2(a0.y); ad[2] = dup2(a0.z); ad[3] = dup2(a0.w);
            ad[4] = dup2(a1.x); ad[5] = dup2(a1.y); ad[6] = dup2(a1.z); ad[7] = dup2(a1.w);
            // B: 12 cols = 3 float4, natural col-pairs as float2
            float4 bb[3];
            bb[0] = Bs4[k][0][tn];
            bb[1] = Bs4[k][1][tn];
            bb[2] = Bs4[k][2][tn];
            const float2* bp = reinterpret_cast<const float2*>(bb);
            #pragma unroll
            for (int j = 0; j < 6; ++j)
                #pragma unroll
                for (int i = 0; i < 8; ++i)
                    fma2(acc[i][j], ad[i], bp[j]);
        }
        __syncthreads();
    }

    // epilogue: bias + relu, scatter to phi[b][moff+n][tn*12..]
    float4 bias4[3];
    #pragma unroll
    for (int q = 0; q < 3; ++q)
        bias4[q] = *reinterpret_cast<const float4*>(bias + tn * 12 + 4 * q);
    const float* bvf = reinterpret_cast<const float*>(bias4);

    #pragma unroll
    for (int i = 0; i < 8; ++i) {
        int row = row0 + rm * 8 + i;
        int bI  = row / NTOK;
        int n   = row - bI * NTOK;
        float* dst = g_phi + ((size_t)bI * L2N + moff + n) * C_ + tn * 12;
        float vv[12];
        #pragma unroll
        for (int j = 0; j < 6; ++j) {
            vv[2 * j]     = fmaxf(acc[i][j].x + bvf[2 * j],     0.f);
            vv[2 * j + 1] = fmaxf(acc[i][j].y + bvf[2 * j + 1], 0.f);
        }
        #pragma unroll
        for (int q = 0; q < 3; ++q)
            *reinterpret_cast<float4*>(dst + 4 * q) =
                make_float4(vv[4 * q], vv[4 * q + 1], vv[4 * q + 2], vv[4 * q + 3]);
    }
}

// ---------------- fused s + W kernel: one block per batch ----------------
__global__ void __launch_bounds__(384) sw_kernel()
{
    const int b = blockIdx.x;
    __shared__ float u4s_s[L2N];
    __shared__ float part[384];
    __shared__ float coef[C_];

    const int tid = threadIdx.x;
    for (int i = tid; i < L2N; i += 384) u4s_s[i] = g_u4s[i];
    __syncthreads();

    const float* __restrict__ pb = g_phi + (size_t)b * PHI_STRIDE;

    {   // pass 1: column sums (s)
        const int c = tid % C_;
        const int h = tid / C_;
        const int m0 = h * NTOK;
        float acc = 0.f;
        #pragma unroll 4
        for (int m = 0; m < NTOK; ++m)
            acc += u4s_s[m0 + m] * pb[(size_t)(m0 + m) * C_ + c];
        part[tid] = acc;
    }
    __syncthreads();
    if (tid < C_) coef[tid] = g_u3[tid] + part[tid] + part[tid + C_];
    __syncthreads();

    // pass 2: per-l dot products (W), one warp per l
    const int warp = tid >> 5, lane = tid & 31;
    const float cc0 = g_c0_s;
    for (int l = warp; l < L2N; l += 12) {
        const float* row = pb + (size_t)l * C_;
        float p = 0.f;
        #pragma unroll
        for (int j = 0; j < 6; ++j) {
            int c = lane + 32 * j;
            p += coef[c] * row[c];
        }
        #pragma unroll
        for (int off = 16; off > 0; off >>= 1)
            p += __shfl_xor_sync(0xffffffffu, p, off);
        if (lane == 0) g_W[(size_t)b * L2N + l] = p + cc0;
    }
}

// ---------------- output: out[b,c,n] = x[b,n,c]*W[b,n] + y[b,n,c]*W[b,n+196] ----------------
__global__ void out_kernel(const float* __restrict__ x, const float* __restrict__ y,
                           float* __restrict__ out)
{
    const int b  = blockIdx.z;
    const int c0 = blockIdx.y * 32;
    const int n0 = blockIdx.x * 32;
    __shared__ float xs[32][33], ys[32][33];
    const int tx = threadIdx.x, ty = threadIdx.y;

    int n = n0 + ty;
    if (n < NTOK) {
        size_t src = ((size_t)b * NTOK + n) * C_ + c0 + tx;
        xs[ty][tx] = x[src];
        ys[ty][tx] = y[src];
    }
    __syncthreads();

    int nn = n0 + tx;
    if (nn < NTOK) {
        float wl = g_W[(size_t)b * L2N + nn];
        float wr = g_W[(size_t)b * L2N + NTOK + nn];
        out[((size_t)b * C_ + c0 + ty) * NTOK + nn] = xs[tx][ty] * wl + ys[tx][ty] * wr;
    }
}

// ---------------- launch ----------------
extern "C" void kernel_launch(void* const* d_in, const int* in_sizes, int n_in,
                              void* d_out, int out_size)
{
    const float* x   = (const float*)d_in[0];
    const float* y   = (const float*)d_in[1];
    const float* w1  = (const float*)d_in[2];
    const float* b1  = (const float*)d_in[3];
    const float* g1  = (const float*)d_in[4];
    const float* be1 = (const float*)d_in[5];
    const float* m1  = (const float*)d_in[6];
    const float* v1  = (const float*)d_in[7];
    const float* w2  = (const float*)d_in[8];
    const float* b2  = (const float*)d_in[9];
    const float* g2  = (const float*)d_in[10];
    const float* be2 = (const float*)d_in[11];
    const float* m2  = (const float*)d_in[12];
    const float* v2  = (const float*)d_in[13];
    const float* w3  = (const float*)d_in[14];
    const float* b3  = (const float*)d_in[15];
    const float* w4  = (const float*)d_in[16];
    const float* b4  = (const float*)d_in[17];
    const float* w5  = (const float*)d_in[18];
    const float* b5  = (const float*)d_in[19];
    float* out = (float*)d_out;

    float *WfT1, *WfT2, *bf1, *bf2;
    cudaGetSymbolAddress((void**)&WfT1, g_WfT1);
    cudaGetSymbolAddress((void**)&WfT2, g_WfT2);
    cudaGetSymbolAddress((void**)&bf1,  g_bf1);
    cudaGetSymbolAddress((void**)&bf2,  g_bf2);

    // order chosen so the ncu single-launch capture lands on gemm_phi
    fold_kernel<<<(C_ * C_ + 255) / 256, 256>>>(w1, b1, g1, be1, m1, v1, WfT1, bf1);
    fold_kernel<<<(C_ * C_ + 255) / 256, 256>>>(w2, b2, g2, be2, m2, v2, WfT2, bf2);
    u3_kernel<<<1, 576>>>(w5, w3);
    gemm_phi<<<dim3(392, 1, 2), 256>>>(x, y);
    u4s_part_kernel<<<56, L2N>>>(w5, w4);
    u4s_reduce_kernel<<<1, L2N>>>();
    c0_kernel<<<1, 1024>>>(w5, b3, b4, b5);
    sw_kernel<<<B_, 384>>>();
    out_kernel<<<dim3(7, 6, B_), dim3(32, 32)>>>(x, y, out);
}

// round 9
// speedup vs baseline: 2.3899x; 1.0207x over previous
#include <cuda_runtime.h>
#include <math.h>

// Problem constants
#define C_    192      // channels
#define NTOK  196      // tokens per stream
#define B_    256      // batch
#define L2N   392      // 2N
#define PHI_STRIDE (L2N * C_)   // 75264 floats per batch

// ---------------- scratch (device globals; no allocation) ----------------
__device__ float g_phi[(size_t)B_ * L2N * C_];   // [B][392][192]  (~77 MB)
__device__ float g_WfT1[C_ * C_];                // folded conv1 weight, transposed [i][o]
__device__ float g_WfT2[C_ * C_];
__device__ float g_bf1[C_];
__device__ float g_bf2[C_];
__device__ float g_u3[C_];
__device__ float g_u4s[L2N];
__device__ float g_u4s_part[56][L2N];
__device__ float g_c0_s;
__device__ float g_W[(size_t)B_ * L2N];          // W[b, l]

// ---------------- packed fp32x2 helpers ----------------
__device__ __forceinline__ void fma2(float2 &d, const float2 &a, const float2 &b) {
    unsigned long long &dr = reinterpret_cast<unsigned long long &>(d);
    const unsigned long long &ar = reinterpret_cast<const unsigned long long &>(const_cast<float2&>(a));
    const unsigned long long &br = reinterpret_cast<const unsigned long long &>(const_cast<float2&>(b));
    asm("fma.rn.f32x2 %0, %1, %2, %0;" : "+l"(dr) : "l"(ar), "l"(br));
}
__device__ __forceinline__ float2 dup2(float v) {
    unsigned long long r;
    asm("mov.b64 %0, {%1, %1};" : "=l"(r) : "f"(v));
    return reinterpret_cast<float2&>(r);
}

// ---------------- tiny precompute kernels ----------------
__global__ void fold_kernel(const float* __restrict__ w, const float* __restrict__ b,
                            const float* __restrict__ g, const float* __restrict__ be,
                            const float* __restrict__ m, const float* __restrict__ v,
                            float* __restrict__ WfT, float* __restrict__ bf)
{
    int tid = blockIdx.x * blockDim.x + threadIdx.x;
    if (tid < C_ * C_) {
        int o = tid / C_, i = tid % C_;
        float inv = g[o] / sqrtf(v[o] + 1e-5f);
        WfT[i * C_ + o] = w[o * C_ + i] * inv;
    }
    if (tid < C_) {
        int o = tid;
        float inv = g[o] / sqrtf(v[o] + 1e-5f);
        bf[o] = (b[o] - m[o]) * inv + be[o];
    }
}

// u3[i] = sum_o w5[o] * w3[o*C+i]  (576 threads: 3-way split over o)
__global__ void u3_kernel(const float* __restrict__ w5, const float* __restrict__ w3)
{
    __shared__ float part[576];
    int tid = threadIdx.x;
    int i = tid % C_;
    int h = tid / C_;          // 0..2
    float acc = 0.f;
    for (int o = h * 64; o < h * 64 + 64; ++o)
        acc += w5[o] * w3[o * C_ + i];
    part[tid] = acc;
    __syncthreads();
    if (tid < C_) g_u3[tid] = part[tid] + part[tid + C_] + part[tid + 2 * C_];
}

// u4s[m] = sum_o w5[192+o] * (w4[o*784+m] + w4[o*784+m+392]) — split-o, 56 blocks
__global__ void u4s_part_kernel(const float* __restrict__ w5, const float* __restrict__ w4)
{
    const int j = blockIdx.x;       // 0..55, owns o in [j*14, j*14+14)
    const int m = threadIdx.x;      // 0..391
    float acc = 0.f;
    #pragma unroll
    for (int oo = 0; oo < 14; ++oo) {
        int o = j * 14 + oo;
        float ws = w5[C_ + o];
        acc += ws * (w4[o * 784 + m] + w4[o * 784 + m + L2N]);
    }
    g_u4s_part[j][m] = acc;
}
__global__ void u4s_reduce_kernel()
{
    const int m = threadIdx.x;
    float acc = 0.f;
    #pragma unroll
    for (int j = 0; j < 56; ++j) acc += g_u4s_part[j][m];
    g_u4s[m] = acc;
}

// c0 = dot(w5[0:192], b3) + dot(w5[192:976], b4) + b5
__global__ void c0_kernel(const float* __restrict__ w5, const float* __restrict__ b3,
                          const float* __restrict__ b4, const float* __restrict__ b5)
{
    __shared__ float red[1024];
    int t = threadIdx.x;
    float p = 0.f;
    if (t < C_) p = w5[t] * b3[t];
    else if (t < C_ + 784) p = w5[t] * b4[t - C_];
    red[t] = p;
    __syncthreads();
    for (int s = 512; s > 0; s >>= 1) {
        if (t < s) red[t] += red[t + s];
        __syncthreads();
    }
    if (t == 0) g_c0_s = red[0] + b5[0];
}

// ---------------- phi GEMM: relu(bn(conv1d)) for both streams ----------------
// Block tile: 128 rows x 192 cols, BK=16, 256 threads = 8 warps (2 per SMSP).
// Microtile: 8 rows x 12 cols per thread; FFMA2 pairs adjacent columns.
// NEW: explicit k-pipelining — register double-buffer of the 5 smem fragments
// so the LDS for k+1 issues before k's 48 FFMA2s (hides the 29-cyc LDS latency
// that capped fma-pipe at 54% with only 2 warps/SMSP).
__global__ void __launch_bounds__(256, 1) gemm_phi(const float* __restrict__ x,
                                                   const float* __restrict__ y)
{
    const int stream = blockIdx.z;
    const float* __restrict__ A    = stream ? y : x;
    const float* __restrict__ Bw   = stream ? g_WfT2 : g_WfT1;
    const float* __restrict__ bias = stream ? g_bf2 : g_bf1;
    const int moff = stream ? NTOK : 0;

    __shared__ float  As[16][128];        // [k][row]   8 KB
    __shared__ float4 Bs4[16][3][16];     // [k][q][cn] 12 KB

    const int tid = threadIdx.x;
    const int tn = tid % 16;              // col group: cols tn*12 .. tn*12+11
    const int rm = tid / 16;              // row group: rows rm*8 .. rm*8+7
    const int row0 = blockIdx.x * 128;

    const float4* Ag = reinterpret_cast<const float4*>(A + (size_t)(row0 + tid) * C_);
    int bkk[3], bq[3], bcn[3], bc4[3];
    #pragma unroll
    for (int j = 0; j < 3; ++j) {
        int f = tid + 256 * j;
        bkk[j] = f / 48;
        bc4[j] = f % 48;
        bq[j]  = bc4[j] % 3;
        bcn[j] = bc4[j] / 3;
    }

    float2 acc[8][6];
    #pragma unroll
    for (int i = 0; i < 8; ++i)
        #pragma unroll
        for (int j = 0; j < 6; ++j) acc[i][j] = make_float2(0.f, 0.f);

    // prefetch tile 0 (global)
    float4 pa[4], pb[3];
    if (tid < 128) {
        #pragma unroll
        for (int j = 0; j < 4; ++j) pa[j] = Ag[j];
    }
    #pragma unroll
    for (int j = 0; j < 3; ++j)
        pb[j] = *reinterpret_cast<const float4*>(Bw + bkk[j] * C_ + bc4[j] * 4);

    #pragma unroll 1
    for (int kt = 0; kt < 12; ++kt) {
        if (tid < 128) {
            #pragma unroll
            for (int j = 0; j < 4; ++j) {
                As[4 * j + 0][tid] = pa[j].x;
                As[4 * j + 1][tid] = pa[j].y;
                As[4 * j + 2][tid] = pa[j].z;
                As[4 * j + 3][tid] = pa[j].w;
            }
        }
        #pragma unroll
        for (int j = 0; j < 3; ++j)
            Bs4[bkk[j]][bq[j]][bcn[j]] = pb[j];
        __syncthreads();

        if (kt < 11) {
            const int q = (kt + 1) * 4;
            if (tid < 128) {
                #pragma unroll
                for (int j = 0; j < 4; ++j) pa[j] = Ag[q + j];
            }
            const int k0 = (kt + 1) * 16;
            #pragma unroll
            for (int j = 0; j < 3; ++j)
                pb[j] = *reinterpret_cast<const float4*>(Bw + (k0 + bkk[j]) * C_ + bc4[j] * 4);
        }

        // ---- software-pipelined k loop: load k+1 before computing k ----
        float4 ca0 = *reinterpret_cast<const float4*>(&As[0][rm * 8]);
        float4 ca1 = *reinterpret_cast<const float4*>(&As[0][rm * 8 + 4]);
        float4 cb0 = Bs4[0][0][tn];
        float4 cb1 = Bs4[0][1][tn];
        float4 cb2 = Bs4[0][2][tn];

        #pragma unroll
        for (int k = 0; k < 16; ++k) {
            float4 na0, na1, nb0, nb1, nb2;
            if (k < 15) {
                na0 = *reinterpret_cast<const float4*>(&As[k + 1][rm * 8]);
                na1 = *reinterpret_cast<const float4*>(&As[k + 1][rm * 8 + 4]);
                nb0 = Bs4[k + 1][0][tn];
                nb1 = Bs4[k + 1][1][tn];
                nb2 = Bs4[k + 1][2][tn];
            }
            float2 ad[8];
            ad[0] = dup2(ca0.x); ad[1] = dup2(ca0.y); ad[2] = dup2(ca0.z); ad[3] = dup2(ca0.w);
            ad[4] = dup2(ca1.x); ad[5] = dup2(ca1.y); ad[6] = dup2(ca1.z); ad[7] = dup2(ca1.w);
            float4 bb[3] = {cb0, cb1, cb2};
            const float2* bp = reinterpret_cast<const float2*>(bb);
            #pragma unroll
            for (int j = 0; j < 6; ++j)
                #pragma unroll
                for (int i = 0; i < 8; ++i)
                    fma2(acc[i][j], ad[i], bp[j]);
            if (k < 15) { ca0 = na0; ca1 = na1; cb0 = nb0; cb1 = nb1; cb2 = nb2; }
        }
        __syncthreads();
    }

    // epilogue: bias + relu, scatter to phi[b][moff+n][tn*12..]
    float4 bias4[3];
    #pragma unroll
    for (int q = 0; q < 3; ++q)
        bias4[q] = *reinterpret_cast<const float4*>(bias + tn * 12 + 4 * q);
    const float* bvf = reinterpret_cast<const float*>(bias4);

    #pragma unroll
    for (int i = 0; i < 8; ++i) {
        int row = row0 + rm * 8 + i;
        int bI  = row / NTOK;
        int n   = row - bI * NTOK;
        float* dst = g_phi + ((size_t)bI * L2N + moff + n) * C_ + tn * 12;
        float vv[12];
        #pragma unroll
        for (int j = 0; j < 6; ++j) {
            vv[2 * j]     = fmaxf(acc[i][j].x + bvf[2 * j],     0.f);
            vv[2 * j + 1] = fmaxf(acc[i][j].y + bvf[2 * j + 1], 0.f);
        }
        #pragma unroll
        for (int q = 0; q < 3; ++q)
            *reinterpret_cast<float4*>(dst + 4 * q) =
                make_float4(vv[4 * q], vv[4 * q + 1], vv[4 * q + 2], vv[4 * q + 3]);
    }
}

// ---------------- fused s + W kernel: 2 blocks per batch, 512 threads ----------------
// blockIdx.y = batch, blockIdx.x = half (pass-2 l-range split).
// Pass 1 (column sums) duplicated in both blocks — second read is L2-hot.
__global__ void __launch_bounds__(512) sw_kernel()
{
    const int b    = blockIdx.y;
    const int half = blockIdx.x;
    __shared__ float u4s_s[L2N];
    __shared__ float part[384];
    __shared__ float coef[C_];

    const int tid = threadIdx.x;
    for (int i = tid; i < L2N; i += 512) u4s_s[i] = g_u4s[i];
    __syncthreads();

    const float* __restrict__ pb = g_phi + (size_t)b * PHI_STRIDE;

    if (tid < 384) {   // pass 1: column sums (s)
        const int c = tid % C_;
        const int h = tid / C_;      // 0 or 1
        const int m0 = h * NTOK;
        float acc = 0.f;
        #pragma unroll 4
        for (int m = 0; m < NTOK; ++m)
            acc += u4s_s[m0 + m] * pb[(size_t)(m0 + m) * C_ + c];
        part[tid] = acc;
    }
    __syncthreads();
    if (tid < C_) coef[tid] = g_u3[tid] + part[tid] + part[tid + C_];
    __syncthreads();

    // pass 2: per-l dot products (W), one warp per l; this block owns 196 l's
    const int warp = tid >> 5, lane = tid & 31;   // 16 warps
    const int lbase = half * NTOK;
    const float cc0 = g_c0_s;
    for (int lo = warp; lo < NTOK; lo += 16) {
        const int l = lbase + lo;
        const float* row = pb + (size_t)l * C_;
        float p = 0.f;
        #pragma unroll
        for (int j = 0; j < 6; ++j) {
            int c = lane + 32 * j;
            p += coef[c] * row[c];
        }
        #pragma unroll
        for (int off = 16; off > 0; off >>= 1)
            p += __shfl_xor_sync(0xffffffffu, p, off);
        if (lane == 0) g_W[(size_t)b * L2N + l] = p + cc0;
    }
}

// ---------------- output: out[b,c,n] = x[b,n,c]*W[b,n] + y[b,n,c]*W[b,n+196] ----------------
__global__ void out_kernel(const float* __restrict__ x, const float* __restrict__ y,
                           float* __restrict__ out)
{
    const int b  = blockIdx.z;
    const int c0 = blockIdx.y * 32;
    const int n0 = blockIdx.x * 32;
    __shared__ float xs[32][33], ys[32][33];
    const int tx = threadIdx.x, ty = threadIdx.y;

    int n = n0 + ty;
    if (n < NTOK) {
        size_t src = ((size_t)b * NTOK + n) * C_ + c0 + tx;
        xs[ty][tx] = x[src];
        ys[ty][tx] = y[src];
    }
    __syncthreads();

    int nn = n0 + tx;
    if (nn < NTOK) {
        float wl = g_W[(size_t)b * L2N + nn];
        float wr = g_W[(size_t)b * L2N + NTOK + nn];
        out[((size_t)b * C_ + c0 + ty) * NTOK + nn] = xs[tx][ty] * wl + ys[tx][ty] * wr;
    }
}

// ---------------- launch ----------------
extern "C" void kernel_launch(void* const* d_in, const int* in_sizes, int n_in,
                              void* d_out, int out_size)
{
    const float* x   = (const float*)d_in[0];
    const float* y   = (const float*)d_in[1];
    const float* w1  = (const float*)d_in[2];
    const float* b1  = (const float*)d_in[3];
    const float* g1  = (const float*)d_in[4];
    const float* be1 = (const float*)d_in[5];
    const float* m1  = (const float*)d_in[6];
    const float* v1  = (const float*)d_in[7];
    const float* w2  = (const float*)d_in[8];
    const float* b2  = (const float*)d_in[9];
    const float* g2  = (const float*)d_in[10];
    const float* be2 = (const float*)d_in[11];
    const float* m2  = (const float*)d_in[12];
    const float* v2  = (const float*)d_in[13];
    const float* w3  = (const float*)d_in[14];
    const float* b3  = (const float*)d_in[15];
    const float* w4  = (const float*)d_in[16];
    const float* b4  = (const float*)d_in[17];
    const float* w5  = (const float*)d_in[18];
    const float* b5  = (const float*)d_in[19];
    float* out = (float*)d_out;

    float *WfT1, *WfT2, *bf1, *bf2;
    cudaGetSymbolAddress((void**)&WfT1, g_WfT1);
    cudaGetSymbolAddress((void**)&WfT2, g_WfT2);
    cudaGetSymbolAddress((void**)&bf1,  g_bf1);
    cudaGetSymbolAddress((void**)&bf2,  g_bf2);

    // order chosen so the ncu single-launch capture lands on gemm_phi
    fold_kernel<<<(C_ * C_ + 255) / 256, 256>>>(w1, b1, g1, be1, m1, v1, WfT1, bf1);
    fold_kernel<<<(C_ * C_ + 255) / 256, 256>>>(w2, b2, g2, be2, m2, v2, WfT2, bf2);
    u3_kernel<<<1, 576>>>(w5, w3);
    gemm_phi<<<dim3(392, 1, 2), 256>>>(x, y);
    u4s_part_kernel<<<56, L2N>>>(w5, w4);
    u4s_reduce_kernel<<<1, L2N>>>();
    c0_kernel<<<1, 1024>>>(w5, b3, b4, b5);
    sw_kernel<<<dim3(2, B_), 512>>>();
    out_kernel<<<dim3(7, 6, B_), dim3(32, 32)>>>(x, y, out);
}

// round 15
// speedup vs baseline: 2.9671x; 1.2415x over previous
#include <cuda_runtime.h>
#include <cuda_bf16.h>
#include <mma.h>
#include <math.h>
#include <stdint.h>

using namespace nvcuda;

// Problem constants
#define C_    192      // channels
#define NTOK  196      // tokens per stream
#define B_    256      // batch
#define L2N   392      // 2N
#define PHI_STRIDE (L2N * C_)   // 75264 floats per batch

// ---------------- scratch (device globals; no allocation) ----------------
__device__ float g_phi[(size_t)B_ * L2N * C_];   // [B][392][192]  (~77 MB)
__device__ __align__(16) __nv_bfloat16 g_Wbh1[C_ * C_];  // bf16 hi of folded w1 [o][i]
__device__ __align__(16) __nv_bfloat16 g_Wbl1[C_ * C_];  // bf16 lo residual
__device__ __align__(16) __nv_bfloat16 g_Wbh2[C_ * C_];
__device__ __align__(16) __nv_bfloat16 g_Wbl2[C_ * C_];
__device__ float g_bf1[C_];
__device__ float g_bf2[C_];
__device__ float g_u3[C_];
__device__ float g_u4s[L2N];
__device__ float g_u4s_part[56][L2N];
__device__ float g_c0_s;
__device__ float g_W[(size_t)B_ * L2N];          // W[b, l]

// ---------------- tiny precompute kernels ----------------
// Fold BN into conv, split to bf16 hi/lo: Wbh/Wbl[o*C+i] = split(w[o*C+i]*inv[o])
__global__ void fold_kernel(const float* __restrict__ w, const float* __restrict__ b,
                            const float* __restrict__ g, const float* __restrict__ be,
                            const float* __restrict__ m, const float* __restrict__ v,
                            __nv_bfloat16* __restrict__ Wbh, __nv_bfloat16* __restrict__ Wbl,
                            float* __restrict__ bf)
{
    int tid = blockIdx.x * blockDim.x + threadIdx.x;
    if (tid < C_ * C_) {
        int o = tid / C_;
        float inv = g[o] / sqrtf(v[o] + 1e-5f);
        float wf = w[tid] * inv;
        __nv_bfloat16 hi = __float2bfloat16(wf);
        Wbh[tid] = hi;
        Wbl[tid] = __float2bfloat16(wf - __bfloat162float(hi));
    }
    if (tid < C_) {
        int o = tid;
        float inv = g[o] / sqrtf(v[o] + 1e-5f);
        bf[o] = (b[o] - m[o]) * inv + be[o];
    }
}

// u3[i] = sum_o w5[o] * w3[o*C+i]
__global__ void u3_kernel(const float* __restrict__ w5, const float* __restrict__ w3)
{
    __shared__ float part[576];
    int tid = threadIdx.x;
    int i = tid % C_;
    int h = tid / C_;
    float acc = 0.f;
    for (int o = h * 64; o < h * 64 + 64; ++o)
        acc += w5[o] * w3[o * C_ + i];
    part[tid] = acc;
    __syncthreads();
    if (tid < C_) g_u3[tid] = part[tid] + part[tid + C_] + part[tid + 2 * C_];
}

__global__ void u4s_part_kernel(const float* __restrict__ w5, const float* __restrict__ w4)
{
    const int j = blockIdx.x;
    const int m = threadIdx.x;
    float acc = 0.f;
    #pragma unroll
    for (int oo = 0; oo < 14; ++oo) {
        int o = j * 14 + oo;
        float ws = w5[C_ + o];
        acc += ws * (w4[o * 784 + m] + w4[o * 784 + m + L2N]);
    }
    g_u4s_part[j][m] = acc;
}
__global__ void u4s_reduce_kernel()
{
    const int m = threadIdx.x;
    float acc = 0.f;
    #pragma unroll
    for (int j = 0; j < 56; ++j) acc += g_u4s_part[j][m];
    g_u4s[m] = acc;
}

__global__ void c0_kernel(const float* __restrict__ w5, const float* __restrict__ b3,
                          const float* __restrict__ b4, const float* __restrict__ b5)
{
    __shared__ float red[1024];
    int t = threadIdx.x;
    float p = 0.f;
    if (t < C_) p = w5[t] * b3[t];
    else if (t < C_ + 784) p = w5[t] * b4[t - C_];
    red[t] = p;
    __syncthreads();
    for (int s = 512; s > 0; s >>= 1) {
        if (t < s) red[t] += red[t + s];
        __syncthreads();
    }
    if (t == 0) g_c0_s = red[0] + b5[0];
}

// ---------------- phi GEMM via wmma HMMA (bf16 split, fp32 accum) ----------------
// phi = relu(Ah*Wh + Ah*Wl + Al*Wh + bias). A split to bf16 hi/lo in the loader.
// Block: 128 rows x 96 cols (half of N), 8 warps; warp = 16 rows x 6 n-tiles.
// K = 192 in 12 chunks of 16. B (hi+lo) staged once in smem; A converted per chunk.
// SMEM (dynamic, bytes):
//   B_HI @0      : 96 x 200 bf16 = 38400
//   B_LO @38400  : 38400
//   A_HI @76800  : 128 x 24 bf16 = 6144
//   A_LO @82944  : 6144            -> total 89088
//   C overlay @0 : 8 warps x 16 x 104 f32 = 53248 (after mma loop, over B region)
#define SM_B_HI 0
#define SM_B_LO 38400
#define SM_A_HI 76800
#define SM_A_LO 82944
#define SMEM_MMA 89088
#define BLDM 200
#define ALDM 24
#define CLDM 104

__global__ void __launch_bounds__(256, 2) gemm_phi_mma(const float* __restrict__ x,
                                                       const float* __restrict__ y)
{
    extern __shared__ char smem[];
    const int stream = blockIdx.z;
    const int half   = blockIdx.y;
    const int row0   = blockIdx.x * 128;
    const float* __restrict__ A = stream ? y : x;
    const __nv_bfloat16* __restrict__ Bh = stream ? g_Wbh2 : g_Wbh1;
    const __nv_bfloat16* __restrict__ Bl = stream ? g_Wbl2 : g_Wbl1;
    const float* __restrict__ bias = stream ? g_bf2 : g_bf1;
    const int moff = stream ? NTOK : 0;

    const int tid = threadIdx.x, warp = tid >> 5, lane = tid & 31;

    __nv_bfloat16* Bh_s = reinterpret_cast<__nv_bfloat16*>(smem + SM_B_HI);
    __nv_bfloat16* Bl_s = reinterpret_cast<__nv_bfloat16*>(smem + SM_B_LO);
    __nv_bfloat16* Ah_s = reinterpret_cast<__nv_bfloat16*>(smem + SM_A_HI);
    __nv_bfloat16* Al_s = reinterpret_cast<__nv_bfloat16*>(smem + SM_A_LO);

    // stage B (hi+lo): rows o in [half*96, half*96+96), all 192 i; ldm BLDM
    for (int i = tid; i < 96 * 24; i += 256) {
        int row = i / 24, q = i % 24;
        const uint4* srch = reinterpret_cast<const uint4*>(Bh + (size_t)(half * 96 + row) * C_ + q * 8);
        const uint4* srcl = reinterpret_cast<const uint4*>(Bl + (size_t)(half * 96 + row) * C_ + q * 8);
        *reinterpret_cast<uint4*>(Bh_s + row * BLDM + q * 8) = *srch;
        *reinterpret_cast<uint4*>(Bl_s + row * BLDM + q * 8) = *srcl;
    }

    wmma::fragment<wmma::accumulator, 16, 16, 16, float> acc[6];
    #pragma unroll
    for (int j = 0; j < 6; ++j) wmma::fill_fragment(acc[j], 0.f);
    __syncthreads();

    #pragma unroll 1
    for (int kc = 0; kc < 12; ++kc) {
        // stage A chunk: 128 rows x 16 cols fp32 -> bf16 hi/lo
        #pragma unroll
        for (int h2 = 0; h2 < 2; ++h2) {
            int f = tid + 256 * h2;          // 0..511
            int row = f >> 2, q = f & 3;
            float4 v = *reinterpret_cast<const float4*>(
                A + (size_t)(row0 + row) * C_ + kc * 16 + q * 4);
            __nv_bfloat162 h01 = __floats2bfloat162_rn(v.x, v.y);
            __nv_bfloat162 h23 = __floats2bfloat162_rn(v.z, v.w);
            float2 f01 = __bfloat1622float2(h01);
            float2 f23 = __bfloat1622float2(h23);
            __nv_bfloat162 l01 = __floats2bfloat162_rn(v.x - f01.x, v.y - f01.y);
            __nv_bfloat162 l23 = __floats2bfloat162_rn(v.z - f23.x, v.w - f23.y);
            uint2 uh, ul;
            uh.x = *reinterpret_cast<uint32_t*>(&h01);
            uh.y = *reinterpret_cast<uint32_t*>(&h23);
            ul.x = *reinterpret_cast<uint32_t*>(&l01);
            ul.y = *reinterpret_cast<uint32_t*>(&l23);
            *reinterpret_cast<uint2*>(Ah_s + row * ALDM + q * 4) = uh;
            *reinterpret_cast<uint2*>(Al_s + row * ALDM + q * 4) = ul;
        }
        __syncthreads();

        wmma::fragment<wmma::matrix_a, 16, 16, 16, __nv_bfloat16, wmma::row_major> a_h, a_l;
        wmma::load_matrix_sync(a_h, Ah_s + warp * 16 * ALDM, ALDM);
        wmma::load_matrix_sync(a_l, Al_s + warp * 16 * ALDM, ALDM);

        #pragma unroll
        for (int j = 0; j < 6; ++j) {
            wmma::fragment<wmma::matrix_b, 16, 16, 16, __nv_bfloat16, wmma::col_major> b_h, b_l;
            wmma::load_matrix_sync(b_h, Bh_s + j * 16 * BLDM + kc * 16, BLDM);
            wmma::load_matrix_sync(b_l, Bl_s + j * 16 * BLDM + kc * 16, BLDM);
            wmma::mma_sync(acc[j], a_h, b_h, acc[j]);
            wmma::mma_sync(acc[j], a_h, b_l, acc[j]);
            wmma::mma_sync(acc[j], a_l, b_h, acc[j]);
        }
        __syncthreads();   // A buffers reused next chunk
    }

    // epilogue: park acc in smem (overlaying retired B region), then bias+relu+store
    float* Cw = reinterpret_cast<float*>(smem) + warp * (16 * CLDM);
    #pragma unroll
    for (int j = 0; j < 6; ++j)
        wmma::store_matrix_sync(Cw + 16 * j, acc[j], CLDM, wmma::mem_row_major);
    // same-warp readback; no cross-warp deps -> no sync needed

    #pragma unroll
    for (int it = 0; it < 12; ++it) {
        int idx = lane + 32 * it;            // 0..383 = 16 rows x 24 quads
        int r = idx / 24, q = idx % 24;
        int row = row0 + warp * 16 + r;
        int bI  = row / NTOK;
        int n   = row - bI * NTOK;
        int c   = half * 96 + q * 4;
        float4 v = *reinterpret_cast<const float4*>(Cw + r * CLDM + q * 4);
        float4 bv = *reinterpret_cast<const float4*>(bias + c);
        float4 o;
        o.x = fmaxf(v.x + bv.x, 0.f);
        o.y = fmaxf(v.y + bv.y, 0.f);
        o.z = fmaxf(v.z + bv.z, 0.f);
        o.w = fmaxf(v.w + bv.w, 0.f);
        *reinterpret_cast<float4*>(g_phi + ((size_t)bI * L2N + moff + n) * C_ + c) = o;
    }
}

// ---------------- fused s + W kernel: 2 blocks per batch, 512 threads ----------------
__global__ void __launch_bounds__(512) sw_kernel()
{
    const int b    = blockIdx.y;
    const int half = blockIdx.x;
    __shared__ float u4s_s[L2N];
    __shared__ float part[384];
    __shared__ float coef[C_];

    const int tid = threadIdx.x;
    for (int i = tid; i < L2N; i += 512) u4s_s[i] = g_u4s[i];
    __syncthreads();

    const float* __restrict__ pb = g_phi + (size_t)b * PHI_STRIDE;

    if (tid < 384) {
        const int c = tid % C_;
        const int h = tid / C_;
        const int m0 = h * NTOK;
        float acc = 0.f;
        #pragma unroll 4
        for (int m = 0; m < NTOK; ++m)
            acc += u4s_s[m0 + m] * pb[(size_t)(m0 + m) * C_ + c];
        part[tid] = acc;
    }
    __syncthreads();
    if (tid < C_) coef[tid] = g_u3[tid] + part[tid] + part[tid + C_];
    __syncthreads();

    const int warp = tid >> 5, lane = tid & 31;
    const int lbase = half * NTOK;
    const float cc0 = g_c0_s;
    for (int lo = warp; lo < NTOK; lo += 16) {
        const int l = lbase + lo;
        const float* row = pb + (size_t)l * C_;
        float p = 0.f;
        #pragma unroll
        for (int j = 0; j < 6; ++j) {
            int c = lane + 32 * j;
            p += coef[c] * row[c];
        }
        #pragma unroll
        for (int off = 16; off > 0; off >>= 1)
            p += __shfl_xor_sync(0xffffffffu, p, off);
        if (lane == 0) g_W[(size_t)b * L2N + l] = p + cc0;
    }
}

// ---------------- output: out[b,c,n] = x[b,n,c]*W[b,n] + y[b,n,c]*W[b,n+196] ----------------
__global__ void out_kernel(const float* __restrict__ x, const float* __restrict__ y,
                           float* __restrict__ out)
{
    const int b  = blockIdx.z;
    const int c0 = blockIdx.y * 32;
    const int n0 = blockIdx.x * 32;
    __shared__ float xs[32][33], ys[32][33];
    const int tx = threadIdx.x, ty = threadIdx.y;

    int n = n0 + ty;
    if (n < NTOK) {
        size_t src = ((size_t)b * NTOK + n) * C_ + c0 + tx;
        xs[ty][tx] = x[src];
        ys[ty][tx] = y[src];
    }
    __syncthreads();

    int nn = n0 + tx;
    if (nn < NTOK) {
        float wl = g_W[(size_t)b * L2N + nn];
        float wr = g_W[(size_t)b * L2N + NTOK + nn];
        out[((size_t)b * C_ + c0 + ty) * NTOK + nn] = xs[tx][ty] * wl + ys[tx][ty] * wr;
    }
}

// ---------------- launch ----------------
extern "C" void kernel_launch(void* const* d_in, const int* in_sizes, int n_in,
                              void* d_out, int out_size)
{
    const float* x   = (const float*)d_in[0];
    const float* y   = (const float*)d_in[1];
    const float* w1  = (const float*)d_in[2];
    const float* b1  = (const float*)d_in[3];
    const float* g1  = (const float*)d_in[4];
    const float* be1 = (const float*)d_in[5];
    const float* m1  = (const float*)d_in[6];
    const float* v1  = (const float*)d_in[7];
    const float* w2  = (const float*)d_in[8];
    const float* b2  = (const float*)d_in[9];
    const float* g2  = (const float*)d_in[10];
    const float* be2 = (const float*)d_in[11];
    const float* m2  = (const float*)d_in[12];
    const float* v2  = (const float*)d_in[13];
    const float* w3  = (const float*)d_in[14];
    const float* b3  = (const float*)d_in[15];
    const float* w4  = (const float*)d_in[16];
    const float* b4  = (const float*)d_in[17];
    const float* w5  = (const float*)d_in[18];
    const float* b5  = (const float*)d_in[19];
    float* out = (float*)d_out;

    __nv_bfloat16 *Wbh1, *Wbl1, *Wbh2, *Wbl2;
    float *bf1, *bf2;
    cudaGetSymbolAddress((void**)&Wbh1, g_Wbh1);
    cudaGetSymbolAddress((void**)&Wbl1, g_Wbl1);
    cudaGetSymbolAddress((void**)&Wbh2, g_Wbh2);
    cudaGetSymbolAddress((void**)&Wbl2, g_Wbl2);
    cudaGetSymbolAddress((void**)&bf1,  g_bf1);
    cudaGetSymbolAddress((void**)&bf2,  g_bf2);

    cudaFuncSetAttribute(gemm_phi_mma, cudaFuncAttributeMaxDynamicSharedMemorySize, SMEM_MMA);

    // order chosen so the ncu single-launch capture lands on gemm_phi_mma
    fold_kernel<<<(C_ * C_ + 255) / 256, 256>>>(w1, b1, g1, be1, m1, v1, Wbh1, Wbl1, bf1);
    fold_kernel<<<(C_ * C_ + 255) / 256, 256>>>(w2, b2, g2, be2, m2, v2, Wbh2, Wbl2, bf2);
    u3_kernel<<<1, 576>>>(w5, w3);
    gemm_phi_mma<<<dim3(392, 2, 2), 256, SMEM_MMA>>>(x, y);
    u4s_part_kernel<<<56, L2N>>>(w5, w4);
    u4s_reduce_kernel<<<1, L2N>>>();
    c0_kernel<<<1, 1024>>>(w5, b3, b4, b5);
    sw_kernel<<<dim3(2, B_), 512>>>();
    out_kernel<<<dim3(7, 6, B_), dim3(32, 32)>>>(x, y, out);
}